// round 10
// baseline (speedup 1.0000x reference)
#include <cuda_runtime.h>
#include <cstdint>

// ---------------------------------------------------------------------------
// ClassificationNCA: 20-step neural cellular automaton, fused per-step kernel.
// Round 10: 1024 threads/CTA (8 warps/SMSP) on the same 128-pixel tile and
// 229KB smem. Each warp: 8 outputs x 64 pixels (2 px/thread). Double-buffered
// weight staging with a 4-register prefetch. Accumulation chains bit-identical
// to all passing rounds (bias -> sequential k per (out,pixel)).
// ---------------------------------------------------------------------------

#define kNCH 29
#define kBatch 16
#define kPix 4096
#define kStateElems (kBatch * kNCH * kPix)
#define kSteps 20

// smem layout (floats)
#define kH1Off 16384              /* region A: P[88][128] / H2[128][128] */
#define kWsOff (kH1Off + 32768)   /* H1 = 256*128 */
#define kWsBuf 4096               /* two 16KB staging buffers */
#define kSmemFloats (kWsOff + 2 * kWsBuf)
#define kSmemBytes (kSmemFloats * 4)   /* 229376 B -> 1 CTA/SM */

__device__ float g_state[2][kStateElems];

// ---------------------------------------------------------------------------
// packed f32x2 helpers
// ---------------------------------------------------------------------------
__device__ __forceinline__ unsigned long long pack2(float x, float y)
{
    unsigned long long r;
    asm("mov.b64 %0, {%1, %2};" : "=l"(r) : "f"(x), "f"(y));
    return r;
}
__device__ __forceinline__ unsigned long long ffma2(unsigned long long a,
                                                    unsigned long long b,
                                                    unsigned long long c)
{
    unsigned long long d;
    asm("fma.rn.f32x2 %0, %1, %2, %3;" : "=l"(d) : "l"(a), "l"(b), "l"(c));
    return d;
}
__device__ __forceinline__ float2 unpack2(unsigned long long v)
{
    float2 f;
    asm("mov.b64 {%0, %1}, %2;" : "=f"(f.x), "=f"(f.y) : "l"(v));
    return f;
}

// ---------------------------------------------------------------------------
// threefry2x32, JAX key schedule (20 rounds)
// ---------------------------------------------------------------------------
#define TF_ROUND(r) { x0 += x1; x1 = (x1 << (r)) | (x1 >> (32 - (r))); x1 ^= x0; }
__host__ __device__ inline void threefry2x32(uint32_t k0, uint32_t k1,
                                             uint32_t x0, uint32_t x1,
                                             uint32_t &o0, uint32_t &o1)
{
    uint32_t k2 = k0 ^ k1 ^ 0x1BD11BDAu;
    x0 += k0; x1 += k1;
    TF_ROUND(13) TF_ROUND(15) TF_ROUND(26) TF_ROUND(6)
    x0 += k1; x1 += k2 + 1u;
    TF_ROUND(17) TF_ROUND(29) TF_ROUND(16) TF_ROUND(24)
    x0 += k2; x1 += k0 + 2u;
    TF_ROUND(13) TF_ROUND(15) TF_ROUND(26) TF_ROUND(6)
    x0 += k0; x1 += k1 + 3u;
    TF_ROUND(17) TF_ROUND(29) TF_ROUND(16) TF_ROUND(24)
    x0 += k1; x1 += k2 + 4u;
    TF_ROUND(13) TF_ROUND(15) TF_ROUND(26) TF_ROUND(6)
    x0 += k2; x1 += k0 + 5u;
    o0 = x0; o1 = x1;
}

// XLA ErfInv (f32), Giles polynomial — matches jax.lax.erf_inv
__device__ inline float erfinv_f(float x)
{
    float w = -log1pf(-x * x);
    float p;
    if (w < 5.0f) {
        w -= 2.5f;
        p = 2.81022636e-08f;
        p = fmaf(p, w, 3.43273939e-07f);
        p = fmaf(p, w, -3.5233877e-06f);
        p = fmaf(p, w, -4.39150654e-06f);
        p = fmaf(p, w, 0.00021858087f);
        p = fmaf(p, w, -0.00125372503f);
        p = fmaf(p, w, -0.00417768164f);
        p = fmaf(p, w, 0.246640727f);
        p = fmaf(p, w, 1.50140941f);
    } else {
        w = sqrtf(w) - 3.0f;
        p = -0.000200214257f;
        p = fmaf(p, w, 0.000100950558f);
        p = fmaf(p, w, 0.00134934322f);
        p = fmaf(p, w, -0.00367342844f);
        p = fmaf(p, w, 0.00573950773f);
        p = fmaf(p, w, -0.0076224613f);
        p = fmaf(p, w, 0.00943887047f);
        p = fmaf(p, w, 1.00167406f);
        p = fmaf(p, w, 2.83297682f);
    }
    return p * x;
}

// ---------------------------------------------------------------------------
// init: channels 0-2 = image (both buffers), 3-18 = threefry normal, 19-28 = 0
// ---------------------------------------------------------------------------
__global__ void __launch_bounds__(256) nca_init_kernel(const float* __restrict__ x,
                                                       uint32_t hk0, uint32_t hk1)
{
    int e = blockIdx.x * 256 + threadIdx.x;
    if (e >= kStateElems) return;
    int b = e / (kNCH * kPix);
    int r = e - b * (kNCH * kPix);
    int c = r / kPix;
    int pix = r - c * kPix;

    if (c < 3) {
        float v = x[(b * 3 + c) * kPix + pix];
        g_state[0][e] = v;
        g_state[1][e] = v;
    } else if (c < 19) {
        const uint32_t HALF = 524288u;  // (16*16*4096)/2
        uint32_t i = (uint32_t)((b * 16 + (c - 3)) * kPix + pix);
        uint32_t lo = (i < HALF) ? i : (i - HALF);
        uint32_t o0, o1;
        threefry2x32(hk0, hk1, lo, lo + HALF, o0, o1);
        uint32_t bits = (i < HALF) ? o0 : o1;
        float f = __uint_as_float((bits >> 9) | 0x3f800000u) - 1.0f;
        const float LOV = -0.99999994f;               // nextafter(-1, 0)
        float u = fmaxf(LOV, f * 2.0f + LOV);         // (hi - lo) rounds to 2.0f
        float z = 1.41421356f * erfinv_f(u);
        g_state[0][e] = 0.5f + 0.225f * z;
    } else {
        g_state[0][e] = 0.0f;
    }
}

// ---------------------------------------------------------------------------
// weight stage stream (transposed Ws[kk*128 + out]):
//  g in [0,8):   layer1, chunk=g>>2, s=g&3, ks=s*22   (22 k x 128 outs, 2816 f)
//  g in [8,16):  layer2, s=g-8, ks=s*32               (32 k x 128 outs, 4096 f)
//  g == 16:      w3 verbatim (3712 floats) into Ws buf0
//  buffer for stage g: Ws + (g&1)*kWsBuf
//  invariant: entering stage-g compute, pf holds stage g+1's weights.
// ---------------------------------------------------------------------------
__device__ __forceinline__ void stage_prefetch(int g, int tid,
    const float* __restrict__ w1, const float* __restrict__ w2,
    const float* __restrict__ w3, float pf[4])
{
    if (g < 8) {
        int chunk = g >> 2, s = g & 3, ks = s * 22;
#pragma unroll
        for (int t = 0; t < 3; ++t) {
            int i = tid + t * 1024;
            if (i < 22 * 128) {
                int kk = i >> 7, ol = i & 127;
                pf[t] = __ldg(&w1[(chunk * 128 + ol) * 88 + ks + kk]);
            }
        }
    } else if (g < 16) {
        int s = g - 8, ks = s * 32;
#pragma unroll
        for (int t = 0; t < 4; ++t) {
            int i = tid + t * 1024;
            int kk = i >> 7, ol = i & 127;
            pf[t] = __ldg(&w2[ol * 256 + ks + kk]);
        }
    } else if (g == 16) {
#pragma unroll
        for (int t = 0; t < 4; ++t) {
            int i = tid + t * 1024;
            if (i < 3712) pf[t] = __ldg(&w3[i]);
        }
    }
}

__device__ __forceinline__ void stage_store(int g, int tid, float* Ws, float pf[4])
{
    if (g < 8) {
        float* buf = Ws + (g & 1) * kWsBuf;
#pragma unroll
        for (int t = 0; t < 3; ++t) {
            int i = tid + t * 1024;
            if (i < 22 * 128) buf[i] = pf[t];
        }
    } else if (g < 16) {
        float* buf = Ws + (g & 1) * kWsBuf;
#pragma unroll
        for (int t = 0; t < 4; ++t) buf[tid + t * 1024] = pf[t];
    } else if (g == 16) {
        // (16&1)==0 -> Ws[0:3712) holds w3 verbatim
#pragma unroll
        for (int t = 0; t < 4; ++t) {
            int i = tid + t * 1024;
            if (i < 3712) Ws[i] = pf[t];
        }
    }
}

// ---------------------------------------------------------------------------
// fused NCA step: perception -> 88->256->128->29 MLP -> fire-masked update
// block = 128 pixels (16x8 tile), 1024 threads, grid (4, 8, 16), 1 CTA/SM
// warp mapping in MLP: ow = warp>>1 (8 outs), ph = warp&1 (64-px half)
// ---------------------------------------------------------------------------
__global__ void __launch_bounds__(1024, 1) nca_step_kernel(
    const float* __restrict__ w1, const float* __restrict__ b1,
    const float* __restrict__ w2, const float* __restrict__ w3,
    float tval, uint32_t fk0, uint32_t fk1, int srcbuf)
{
    extern __shared__ float smem[];
    float* P   = smem;           // [88][128]
    float* H1s = smem + kH1Off;  // [256][128]
    float* H2s = smem;           // [128][128] (reuses P region)
    float* Ws  = smem + kWsOff;  // 2 x 4096-float staging buffers

    const float* __restrict__ src = g_state[srcbuf];
    float* __restrict__ dst = g_state[srcbuf ^ 1];

    const int tid = threadIdx.x;
    const int b  = blockIdx.z;
    const int x0 = blockIdx.x * 16;
    const int y0 = blockIdx.y * 8;
    const int pix  = tid & 127;
    const int grp8 = tid >> 7;          // 0..7
    const int tx = pix & 15;
    const int ty = pix >> 4;
    const int gx = x0 + tx;
    const int gy = y0 + ty;

    float pf[4];
    // prefetch stage 0; its latency overlaps perception's global loads
    stage_prefetch(0, tid, w1, w2, w3, pf);

    // ---- phase 1: perception (s, sobel_x, sobel_y, t) -> P ----
    {
        const float* sb = src + b * (kNCH * kPix);
        const int cbeg = grp8 * 4;
        const int cend = (cbeg + 4 < 29) ? cbeg + 4 : 29;
        const bool ym = gy > 0, yp = gy < 63, xm = gx > 0, xp = gx < 63;
        for (int c = cbeg; c < cend; ++c) {
            const float* sc = sb + c * kPix;
            float v11 = __ldg(&sc[gy * 64 + gx]);
            float v01 = ym ? __ldg(&sc[(gy - 1) * 64 + gx]) : 0.f;
            float v21 = yp ? __ldg(&sc[(gy + 1) * 64 + gx]) : 0.f;
            float v10 = xm ? __ldg(&sc[gy * 64 + gx - 1]) : 0.f;
            float v12 = xp ? __ldg(&sc[gy * 64 + gx + 1]) : 0.f;
            float v00 = (ym && xm) ? __ldg(&sc[(gy - 1) * 64 + gx - 1]) : 0.f;
            float v02 = (ym && xp) ? __ldg(&sc[(gy - 1) * 64 + gx + 1]) : 0.f;
            float v20 = (yp && xm) ? __ldg(&sc[(gy + 1) * 64 + gx - 1]) : 0.f;
            float v22 = (yp && xp) ? __ldg(&sc[(gy + 1) * 64 + gx + 1]) : 0.f;
            float sx = ((v02 - v00) + 2.0f * (v12 - v10) + (v22 - v20)) * 0.125f;
            float sy = ((v20 - v00) + 2.0f * (v21 - v01) + (v22 - v02)) * 0.125f;
            P[c * 128 + pix] = v11;
            P[(29 + c) * 128 + pix] = sx;
            P[(58 + c) * 128 + pix] = sy;
        }
        if (grp8 == 0) P[87 * 128 + pix] = tval;
    }

    stage_store(0, tid, Ws, pf);
    stage_prefetch(1, tid, w1, w2, w3, pf);
    __syncthreads();   // P ready, Ws buf0 ready

    const int wrp = tid >> 5;            // 0..31
    const int ow  = wrp >> 1;            // 0..15 (uniform -> broadcast LDS)
    const int ph  = wrp & 1;             // pixel half
    const int pb  = ph * 64 + (tid & 31) * 2;   // 2 pixels / thread

    // ---- layer 1: h1 = leaky(W1 @ p + b1), 256 outs, k = 88 (2 chunks x 4x22) ----
    for (int c = 0; c < 2; ++c) {
        const int obase = c * 128 + ow * 8;      // global out base (8 outs)
        unsigned long long acc[4][2];
#pragma unroll
        for (int p = 0; p < 4; ++p) {
            unsigned long long bp = pack2(__ldg(&b1[obase + 2 * p]),
                                          __ldg(&b1[obase + 2 * p + 1]));
            acc[p][0] = bp; acc[p][1] = bp;
        }
        for (int s = 0; s < 4; ++s) {
            const int g = c * 4 + s;
            const float* buf = Ws + (g & 1) * kWsBuf;
            const int ks = s * 22;
#pragma unroll 2
            for (int kk = 0; kk < 22; ++kk) {
                float2 pv = *reinterpret_cast<const float2*>(&P[(ks + kk) * 128 + pb]);
                const ulonglong2 wA = *reinterpret_cast<const ulonglong2*>(&buf[kk * 128 + ow * 8]);
                const ulonglong2 wB = *reinterpret_cast<const ulonglong2*>(&buf[kk * 128 + ow * 8 + 4]);
                unsigned long long p0 = pack2(pv.x, pv.x);
                unsigned long long p1 = pack2(pv.y, pv.y);
                acc[0][0] = ffma2(wA.x, p0, acc[0][0]);
                acc[0][1] = ffma2(wA.x, p1, acc[0][1]);
                acc[1][0] = ffma2(wA.y, p0, acc[1][0]);
                acc[1][1] = ffma2(wA.y, p1, acc[1][1]);
                acc[2][0] = ffma2(wB.x, p0, acc[2][0]);
                acc[2][1] = ffma2(wB.x, p1, acc[2][1]);
                acc[3][0] = ffma2(wB.y, p0, acc[3][0]);
                acc[3][1] = ffma2(wB.y, p1, acc[3][1]);
            }
            stage_store(g + 1, tid, Ws, pf);
            stage_prefetch(g + 2, tid, w1, w2, w3, pf);
            __syncthreads();
        }
#pragma unroll
        for (int p = 0; p < 4; ++p) {
            float2 f0 = unpack2(acc[p][0]);   // (out 2p, out 2p+1) @ pixel pb+0
            float2 f1 = unpack2(acc[p][1]);   // (out 2p, out 2p+1) @ pixel pb+1
            float a0 = f0.x >= 0.f ? f0.x : 0.01f * f0.x;
            float a1 = f1.x >= 0.f ? f1.x : 0.01f * f1.x;
            float b0v = f0.y >= 0.f ? f0.y : 0.01f * f0.y;
            float b1v = f1.y >= 0.f ? f1.y : 0.01f * f1.y;
            *reinterpret_cast<float2*>(&H1s[(obase + 2 * p) * 128 + pb]) = make_float2(a0, a1);
            *reinterpret_cast<float2*>(&H1s[(obase + 2 * p + 1) * 128 + pb]) = make_float2(b0v, b1v);
        }
    }
    __syncthreads();   // all H1 visible before layer2 reads it

    // ---- layer 2: h2 = leaky(W2 @ h1), 128 outs, k = 256 (8 x 32) ----
    {
        const int obase = ow * 8;
        unsigned long long acc[4][2];
#pragma unroll
        for (int p = 0; p < 4; ++p) { acc[p][0] = 0ull; acc[p][1] = 0ull; }
        for (int s = 0; s < 8; ++s) {
            const int g = 8 + s;
            const float* buf = Ws + (g & 1) * kWsBuf;
            const int ks = s * 32;
#pragma unroll 2
            for (int kk = 0; kk < 32; ++kk) {
                float2 hv = *reinterpret_cast<const float2*>(&H1s[(ks + kk) * 128 + pb]);
                const ulonglong2 wA = *reinterpret_cast<const ulonglong2*>(&buf[kk * 128 + ow * 8]);
                const ulonglong2 wB = *reinterpret_cast<const ulonglong2*>(&buf[kk * 128 + ow * 8 + 4]);
                unsigned long long p0 = pack2(hv.x, hv.x);
                unsigned long long p1 = pack2(hv.y, hv.y);
                acc[0][0] = ffma2(wA.x, p0, acc[0][0]);
                acc[0][1] = ffma2(wA.x, p1, acc[0][1]);
                acc[1][0] = ffma2(wA.y, p0, acc[1][0]);
                acc[1][1] = ffma2(wA.y, p1, acc[1][1]);
                acc[2][0] = ffma2(wB.x, p0, acc[2][0]);
                acc[2][1] = ffma2(wB.x, p1, acc[2][1]);
                acc[3][0] = ffma2(wB.y, p0, acc[3][0]);
                acc[3][1] = ffma2(wB.y, p1, acc[3][1]);
            }
            stage_store(g + 1, tid, Ws, pf);   // g=15 stores w3 into Ws buf0
            stage_prefetch(g + 2, tid, w1, w2, w3, pf);
            __syncthreads();
        }
#pragma unroll
        for (int p = 0; p < 4; ++p) {
            float2 f0 = unpack2(acc[p][0]);
            float2 f1 = unpack2(acc[p][1]);
            float a0 = f0.x >= 0.f ? f0.x : 0.01f * f0.x;
            float a1 = f1.x >= 0.f ? f1.x : 0.01f * f1.x;
            float b0v = f0.y >= 0.f ? f0.y : 0.01f * f0.y;
            float b1v = f1.y >= 0.f ? f1.y : 0.01f * f1.y;
            *reinterpret_cast<float2*>(&H2s[(obase + 2 * p) * 128 + pb]) = make_float2(a0, a1);
            *reinterpret_cast<float2*>(&H2s[(obase + 2 * p + 1) * 128 + pb]) = make_float2(b0v, b1v);
        }
    }
    __syncthreads();   // H2 + staged w3 visible

    // ---- layer 3 (channels 3..28 only; 0..2 are masked) + fire update ----
    {
        // grp8 0..7 handle {4,4,3,3,3,3,3,3} channels starting at {3,7,11,14,17,20,23,26}
        const int obase = (grp8 < 2) ? (3 + grp8 * 4) : (11 + (grp8 - 2) * 3);
        const int cnt   = (grp8 < 2) ? 4 : 3;
        float dxv[4];
#pragma unroll
        for (int u = 0; u < 4; ++u) dxv[u] = 0.f;
#pragma unroll 2
        for (int k = 0; k < 128; ++k) {
            float h = H2s[k * 128 + pix];
#pragma unroll
            for (int u = 0; u < 4; ++u)
                dxv[u] = fmaf(Ws[(obase + u) * 128 + k], h, dxv[u]);
        }
        // fire mask: uniform(fold_in(key, step), (B,H,W,1)) < 0.5  <=>  top bit 0
        uint32_t n = (uint32_t)(b * 4096 + gy * 64 + gx);
        const uint32_t HALF = 32768u;
        uint32_t lo = (n < HALF) ? n : (n - HALF);
        uint32_t o0, o1;
        threefry2x32(fk0, fk1, lo, lo + HALF, o0, o1);
        uint32_t bits = (n < HALF) ? o0 : o1;
        bool fire = (bits & 0x80000000u) == 0u;

        int base = (b * kNCH) * kPix + gy * 64 + gx;
#pragma unroll
        for (int u = 0; u < 4; ++u) {
            if (u < cnt) {
                int idx = base + (obase + u) * kPix;
                float s = __ldg(&src[idx]);
                dst[idx] = fire ? (s + dxv[u]) : s;
            }
        }
    }
}

// ---------------------------------------------------------------------------
// reduce: mean over HW of channels 19..28, then softmax -> out (16, 10)
// ---------------------------------------------------------------------------
__global__ void __launch_bounds__(256) nca_reduce_kernel(float* __restrict__ out)
{
    int b = blockIdx.x;
    int tid = threadIdx.x;
    const float* st = g_state[0] + (b * kNCH + 19) * kPix;
    float acc[10];
#pragma unroll
    for (int c = 0; c < 10; ++c) acc[c] = 0.f;
    for (int i = tid; i < kPix; i += 256) {
#pragma unroll
        for (int c = 0; c < 10; ++c) acc[c] += st[c * kPix + i];
    }
#pragma unroll
    for (int c = 0; c < 10; ++c) {
#pragma unroll
        for (int off = 16; off > 0; off >>= 1)
            acc[c] += __shfl_xor_sync(0xffffffffu, acc[c], off);
    }
    __shared__ float sred[10][8];
    int wid = tid >> 5, lane = tid & 31;
    if (lane == 0) {
#pragma unroll
        for (int c = 0; c < 10; ++c) sred[c][wid] = acc[c];
    }
    __syncthreads();
    if (tid == 0) {
        float m[10];
        float mx = -1e30f;
#pragma unroll
        for (int c = 0; c < 10; ++c) {
            float s = 0.f;
#pragma unroll
            for (int w = 0; w < 8; ++w) s += sred[c][w];
            m[c] = s * (1.0f / 4096.0f);
            mx = fmaxf(mx, m[c]);
        }
        float den = 0.f;
        float e[10];
#pragma unroll
        for (int c = 0; c < 10; ++c) { e[c] = expf(m[c] - mx); den += e[c]; }
#pragma unroll
        for (int c = 0; c < 10; ++c) out[b * 10 + c] = e[c] / den;
    }
}

// ---------------------------------------------------------------------------
extern "C" void kernel_launch(void* const* d_in, const int* in_sizes, int n_in,
                              void* d_out, int out_size)
{
    (void)in_sizes; (void)n_in; (void)out_size;
    const float* x  = (const float*)d_in[0];
    const float* w1 = (const float*)d_in[1];
    const float* b1 = (const float*)d_in[2];
    const float* w2 = (const float*)d_in[3];
    const float* w3 = (const float*)d_in[4];
    float* out = (float*)d_out;

    cudaFuncSetAttribute(nca_step_kernel,
                         cudaFuncAttributeMaxDynamicSharedMemorySize, kSmemBytes);

    // hid-init key: fold_in(key(42), 10000)
    uint32_t hk0, hk1;
    threefry2x32(0u, 42u, 0u, 10000u, hk0, hk1);
    nca_init_kernel<<<(kStateElems + 255) / 256, 256>>>(x, hk0, hk1);

    for (int s = 0; s < kSteps; ++s) {
        uint32_t fk0, fk1;
        threefry2x32(0u, 42u, 0u, (uint32_t)s, fk0, fk1);
        nca_step_kernel<<<dim3(4, 8, 16), 1024, kSmemBytes>>>(
            w1, b1, w2, w3, (float)s / 100.0f, fk0, fk1, s & 1);
    }
    nca_reduce_kernel<<<16, 256>>>(out);
}

// round 13
// speedup vs baseline: 2.0497x; 2.0497x over previous
#include <cuda_runtime.h>
#include <cstdint>

// ---------------------------------------------------------------------------
// ClassificationNCA: 20-step NCA. Round 13 = round 11 with the smem overrun
// fixed (Ws restored to 8192 floats, round-4 staging verbatim).
// Kernel A: per-step fire eval + compaction + copy-through of non-firing px.
// Kernel B: round-4 MLP kernel run only on firing pixels (~2 waves vs 4).
// MLP accumulation chains bit-identical to all passing rounds.
// ---------------------------------------------------------------------------

#define kNCH 29
#define kBatch 16
#define kPix 4096
#define kStateElems (kBatch * kNCH * kPix)
#define kSteps 20
#define kTilesPerBatch 20   /* 20*128 = 2560 slot capacity ~ mean+16 sigma */

// smem layout (floats) — identical to round 4
#define kH1Off 16384              /* region A: P[88][128] / H2[128][128] */
#define kWsOff (kH1Off + 32768)   /* H1 = 256*128 */
#define kWsFloats 8192
#define kSmemFloats (kWsOff + kWsFloats)
#define kSmemBytes (kSmemFloats * 4) /* 229376 B -> 1 CTA/SM */

__device__ float g_state[2][kStateElems];
__device__ int g_cnt[kSteps][kBatch];
__device__ uint16_t g_plist[kBatch][kPix];

// ---------------------------------------------------------------------------
// packed f32x2 helpers
// ---------------------------------------------------------------------------
__device__ __forceinline__ unsigned long long pack2(float x, float y)
{
    unsigned long long r;
    asm("mov.b64 %0, {%1, %2};" : "=l"(r) : "f"(x), "f"(y));
    return r;
}
__device__ __forceinline__ unsigned long long ffma2(unsigned long long a,
                                                    unsigned long long b,
                                                    unsigned long long c)
{
    unsigned long long d;
    asm("fma.rn.f32x2 %0, %1, %2, %3;" : "=l"(d) : "l"(a), "l"(b), "l"(c));
    return d;
}
__device__ __forceinline__ float2 unpack2(unsigned long long v)
{
    float2 f;
    asm("mov.b64 {%0, %1}, %2;" : "=f"(f.x), "=f"(f.y) : "l"(v));
    return f;
}

// ---------------------------------------------------------------------------
// threefry2x32, JAX key schedule (20 rounds)
// ---------------------------------------------------------------------------
#define TF_ROUND(r) { x0 += x1; x1 = (x1 << (r)) | (x1 >> (32 - (r))); x1 ^= x0; }
__host__ __device__ inline void threefry2x32(uint32_t k0, uint32_t k1,
                                             uint32_t x0, uint32_t x1,
                                             uint32_t &o0, uint32_t &o1)
{
    uint32_t k2 = k0 ^ k1 ^ 0x1BD11BDAu;
    x0 += k0; x1 += k1;
    TF_ROUND(13) TF_ROUND(15) TF_ROUND(26) TF_ROUND(6)
    x0 += k1; x1 += k2 + 1u;
    TF_ROUND(17) TF_ROUND(29) TF_ROUND(16) TF_ROUND(24)
    x0 += k2; x1 += k0 + 2u;
    TF_ROUND(13) TF_ROUND(15) TF_ROUND(26) TF_ROUND(6)
    x0 += k0; x1 += k1 + 3u;
    TF_ROUND(17) TF_ROUND(29) TF_ROUND(16) TF_ROUND(24)
    x0 += k1; x1 += k2 + 4u;
    TF_ROUND(13) TF_ROUND(15) TF_ROUND(26) TF_ROUND(6)
    x0 += k2; x1 += k0 + 5u;
    o0 = x0; o1 = x1;
}

// XLA ErfInv (f32), Giles polynomial — matches jax.lax.erf_inv
__device__ inline float erfinv_f(float x)
{
    float w = -log1pf(-x * x);
    float p;
    if (w < 5.0f) {
        w -= 2.5f;
        p = 2.81022636e-08f;
        p = fmaf(p, w, 3.43273939e-07f);
        p = fmaf(p, w, -3.5233877e-06f);
        p = fmaf(p, w, -4.39150654e-06f);
        p = fmaf(p, w, 0.00021858087f);
        p = fmaf(p, w, -0.00125372503f);
        p = fmaf(p, w, -0.00417768164f);
        p = fmaf(p, w, 0.246640727f);
        p = fmaf(p, w, 1.50140941f);
    } else {
        w = sqrtf(w) - 3.0f;
        p = -0.000200214257f;
        p = fmaf(p, w, 0.000100950558f);
        p = fmaf(p, w, 0.00134934322f);
        p = fmaf(p, w, -0.00367342844f);
        p = fmaf(p, w, 0.00573950773f);
        p = fmaf(p, w, -0.0076224613f);
        p = fmaf(p, w, 0.00943887047f);
        p = fmaf(p, w, 1.00167406f);
        p = fmaf(p, w, 2.83297682f);
    }
    return p * x;
}

// ---------------------------------------------------------------------------
// init: channels 0-2 = image (both buffers), 3-18 = threefry normal, 19-28 = 0
// also zeroes g_cnt (per launch -> graph-replay safe).
// ---------------------------------------------------------------------------
__global__ void __launch_bounds__(256) nca_init_kernel(const float* __restrict__ x,
                                                       uint32_t hk0, uint32_t hk1)
{
    int e = blockIdx.x * 256 + threadIdx.x;
    if (e >= kStateElems) return;
    if (e < kSteps * kBatch) ((int*)g_cnt)[e] = 0;
    int b = e / (kNCH * kPix);
    int r = e - b * (kNCH * kPix);
    int c = r / kPix;
    int pix = r - c * kPix;

    if (c < 3) {
        float v = x[(b * 3 + c) * kPix + pix];
        g_state[0][e] = v;
        g_state[1][e] = v;
    } else if (c < 19) {
        const uint32_t HALF = 524288u;  // (16*16*4096)/2
        uint32_t i = (uint32_t)((b * 16 + (c - 3)) * kPix + pix);
        uint32_t lo = (i < HALF) ? i : (i - HALF);
        uint32_t o0, o1;
        threefry2x32(hk0, hk1, lo, lo + HALF, o0, o1);
        uint32_t bits = (i < HALF) ? o0 : o1;
        float f = __uint_as_float((bits >> 9) | 0x3f800000u) - 1.0f;
        const float LOV = -0.99999994f;               // nextafter(-1, 0)
        float u = fmaxf(LOV, f * 2.0f + LOV);         // (hi - lo) rounds to 2.0f
        float z = 1.41421356f * erfinv_f(u);
        g_state[0][e] = 0.5f + 0.225f * z;
    } else {
        g_state[0][e] = 0.0f;
    }
}

// ---------------------------------------------------------------------------
// Kernel A: fire mask + compaction + copy-through for non-firing pixels.
// grid 64 x 1024 threads = 65536 pixels. One warp spans 32 px of one batch.
// ---------------------------------------------------------------------------
__global__ void __launch_bounds__(1024) nca_fire_kernel(uint32_t fk0, uint32_t fk1,
                                                        int step, int srcbuf)
{
    int e = blockIdx.x * 1024 + threadIdx.x;
    int b = e >> 12;
    int pix = e & 4095;

    // fire: uniform(fold_in(key, step), (B,H,W,1)) < 0.5  <=>  top bit 0
    const uint32_t HALF = 32768u;
    uint32_t n = (uint32_t)e;
    uint32_t lo = (n < HALF) ? n : (n - HALF);
    uint32_t o0, o1;
    threefry2x32(fk0, fk1, lo, lo + HALF, o0, o1);
    uint32_t bits = (n < HALF) ? o0 : o1;
    bool fire = (bits & 0x80000000u) == 0u;

    unsigned mask = __ballot_sync(0xffffffffu, fire);
    int lane = threadIdx.x & 31;
    int base = 0;
    if (lane == 0) base = atomicAdd(&g_cnt[step][b], __popc(mask));
    base = __shfl_sync(0xffffffffu, base, 0);

    if (fire) {
        g_plist[b][base + __popc(mask & ((1u << lane) - 1u))] = (uint16_t)pix;
    } else {
        const float* __restrict__ src = g_state[srcbuf];
        float* __restrict__ dst = g_state[srcbuf ^ 1];
        int idx = b * (kNCH * kPix) + 3 * kPix + pix;
#pragma unroll
        for (int c = 0; c < 26; ++c) {
            dst[idx] = __ldg(&src[idx]);
            idx += kPix;
        }
    }
}

// ---------------------------------------------------------------------------
// Kernel B: fused NCA step on COMPACTED firing pixels.
// Round-4 MLP body verbatim; 128 slots/CTA, 512 threads, grid (20, 16).
// ---------------------------------------------------------------------------
__global__ void __launch_bounds__(512, 1) nca_step_kernel(
    const float* __restrict__ w1, const float* __restrict__ b1,
    const float* __restrict__ w2, const float* __restrict__ w3,
    float tval, int step, int srcbuf)
{
    extern __shared__ float smem[];
    float* P   = smem;           // [88][128]
    float* H1s = smem + kH1Off;  // [256][128]
    float* H2s = smem;           // [128][128] (reuses P region)
    float* Ws  = smem + kWsOff;  // weight staging, 8192 floats

    const int b = blockIdx.y;
    const int nf = g_cnt[step][b];
    const int sbase = blockIdx.x * 128;
    if (sbase >= nf) return;

    const float* __restrict__ src = g_state[srcbuf];
    float* __restrict__ dst = g_state[srcbuf ^ 1];

    const int tid = threadIdx.x;
    const int pix  = tid & 127;          // slot-local index
    const int grp4 = tid >> 7;           // 0..3
    const int slot = sbase + pix;
    const bool real = slot < nf;
    const int px = (int)g_plist[b][slot];   // stale-but-valid (<=4095) if !real
    const int gx = px & 63;
    const int gy = px >> 6;

    // ---- phase 1: perception (s, sobel_x, sobel_y, t) -> P ----
    {
        const float* sb = src + b * (kNCH * kPix);
        const int cbeg = grp4 * 8;
        const int cend = (cbeg + 8 < 29) ? cbeg + 8 : 29;
        const bool ym = gy > 0, yp = gy < 63, xm = gx > 0, xp = gx < 63;
        for (int c = cbeg; c < cend; ++c) {
            const float* sc = sb + c * kPix;
            float v11 = __ldg(&sc[gy * 64 + gx]);
            float v01 = ym ? __ldg(&sc[(gy - 1) * 64 + gx]) : 0.f;
            float v21 = yp ? __ldg(&sc[(gy + 1) * 64 + gx]) : 0.f;
            float v10 = xm ? __ldg(&sc[gy * 64 + gx - 1]) : 0.f;
            float v12 = xp ? __ldg(&sc[gy * 64 + gx + 1]) : 0.f;
            float v00 = (ym && xm) ? __ldg(&sc[(gy - 1) * 64 + gx - 1]) : 0.f;
            float v02 = (ym && xp) ? __ldg(&sc[(gy - 1) * 64 + gx + 1]) : 0.f;
            float v20 = (yp && xm) ? __ldg(&sc[(gy + 1) * 64 + gx - 1]) : 0.f;
            float v22 = (yp && xp) ? __ldg(&sc[(gy + 1) * 64 + gx + 1]) : 0.f;
            float sx = ((v02 - v00) + 2.0f * (v12 - v10) + (v22 - v20)) * 0.125f;
            float sy = ((v20 - v00) + 2.0f * (v21 - v01) + (v22 - v02)) * 0.125f;
            P[c * 128 + pix] = v11;
            P[(29 + c) * 128 + pix] = sx;
            P[(58 + c) * 128 + pix] = sy;
        }
        if (grp4 == 0) P[87 * 128 + pix] = tval;
    }

    const int og = tid >> 5;   // warp id 0..15 (uniform -> broadcast LDS)
    const int pb = (tid & 31) << 2;  // slot base, 4 slots / thread

    // ---- layer 1: h1 = leaky(W1 @ p + b1), 256 outs, k = 88 ----
    for (int chunk = 0; chunk < 2; ++chunk) {
        const int obase = og * 16 + chunk * 8;
        unsigned long long acc[4][4];
#pragma unroll
        for (int p = 0; p < 4; ++p) {
            unsigned long long bp = pack2(__ldg(&b1[obase + 2 * p]),
                                          __ldg(&b1[obase + 2 * p + 1]));
            acc[p][0] = bp; acc[p][1] = bp; acc[p][2] = bp; acc[p][3] = bp;
        }
        for (int ks = 0; ks < 88; ks += 44) {
            __syncthreads();
            // stage transposed: Ws[kk*128 + ol], ol -> weight row for this chunk
            for (int i = tid; i < 44 * 128; i += 512) {
                int kk = i >> 7;
                int ol = i & 127;
                int row = (ol >> 3) * 16 + chunk * 8 + (ol & 7);
                Ws[i] = __ldg(&w1[row * 88 + ks + kk]);
            }
            __syncthreads();
#pragma unroll 2
            for (int kk = 0; kk < 44; ++kk) {
                float4 pv = *reinterpret_cast<const float4*>(&P[(ks + kk) * 128 + pb]);
                const ulonglong2 wA = *reinterpret_cast<const ulonglong2*>(&Ws[kk * 128 + og * 8]);
                const ulonglong2 wB = *reinterpret_cast<const ulonglong2*>(&Ws[kk * 128 + og * 8 + 4]);
                unsigned long long px4[4];
                px4[0] = pack2(pv.x, pv.x); px4[1] = pack2(pv.y, pv.y);
                px4[2] = pack2(pv.z, pv.z); px4[3] = pack2(pv.w, pv.w);
#pragma unroll
                for (int j = 0; j < 4; ++j) {
                    acc[0][j] = ffma2(wA.x, px4[j], acc[0][j]);
                    acc[1][j] = ffma2(wA.y, px4[j], acc[1][j]);
                    acc[2][j] = ffma2(wB.x, px4[j], acc[2][j]);
                    acc[3][j] = ffma2(wB.y, px4[j], acc[3][j]);
                }
            }
        }
#pragma unroll
        for (int p = 0; p < 4; ++p) {
            float lo4[4], hi4[4];
#pragma unroll
            for (int j = 0; j < 4; ++j) {
                float2 f = unpack2(acc[p][j]);
                lo4[j] = f.x >= 0.f ? f.x : 0.01f * f.x;
                hi4[j] = f.y >= 0.f ? f.y : 0.01f * f.y;
            }
            *reinterpret_cast<float4*>(&H1s[(obase + 2 * p) * 128 + pb]) =
                make_float4(lo4[0], lo4[1], lo4[2], lo4[3]);
            *reinterpret_cast<float4*>(&H1s[(obase + 2 * p + 1) * 128 + pb]) =
                make_float4(hi4[0], hi4[1], hi4[2], hi4[3]);
        }
    }

    // ---- layer 2: h2 = leaky(W2 @ h1), 128 outs, k = 256 ----
    {
        const int obase = og * 8;
        unsigned long long acc[4][4];
#pragma unroll
        for (int p = 0; p < 4; ++p) {
            acc[p][0] = 0ull; acc[p][1] = 0ull; acc[p][2] = 0ull; acc[p][3] = 0ull;
        }
        for (int ks = 0; ks < 256; ks += 64) {
            __syncthreads();
            for (int i = tid; i < 64 * 128; i += 512) {
                int kk = i >> 7;
                int ol = i & 127;
                Ws[i] = __ldg(&w2[ol * 256 + ks + kk]);
            }
            __syncthreads();
#pragma unroll 2
            for (int kk = 0; kk < 64; ++kk) {
                float4 hv = *reinterpret_cast<const float4*>(&H1s[(ks + kk) * 128 + pb]);
                const ulonglong2 wA = *reinterpret_cast<const ulonglong2*>(&Ws[kk * 128 + og * 8]);
                const ulonglong2 wB = *reinterpret_cast<const ulonglong2*>(&Ws[kk * 128 + og * 8 + 4]);
                unsigned long long px4[4];
                px4[0] = pack2(hv.x, hv.x); px4[1] = pack2(hv.y, hv.y);
                px4[2] = pack2(hv.z, hv.z); px4[3] = pack2(hv.w, hv.w);
#pragma unroll
                for (int j = 0; j < 4; ++j) {
                    acc[0][j] = ffma2(wA.x, px4[j], acc[0][j]);
                    acc[1][j] = ffma2(wA.y, px4[j], acc[1][j]);
                    acc[2][j] = ffma2(wB.x, px4[j], acc[2][j]);
                    acc[3][j] = ffma2(wB.y, px4[j], acc[3][j]);
                }
            }
        }
#pragma unroll
        for (int p = 0; p < 4; ++p) {
            float lo4[4], hi4[4];
#pragma unroll
            for (int j = 0; j < 4; ++j) {
                float2 f = unpack2(acc[p][j]);
                lo4[j] = f.x >= 0.f ? f.x : 0.01f * f.x;
                hi4[j] = f.y >= 0.f ? f.y : 0.01f * f.y;
            }
            *reinterpret_cast<float4*>(&H2s[(obase + 2 * p) * 128 + pb]) =
                make_float4(lo4[0], lo4[1], lo4[2], lo4[3]);
            *reinterpret_cast<float4*>(&H2s[(obase + 2 * p + 1) * 128 + pb]) =
                make_float4(hi4[0], hi4[1], hi4[2], hi4[3]);
        }
    }

    // ---- layer 3 (channels 3..28) + unconditional update of firing px ----
    __syncthreads();
    for (int i = tid; i < 29 * 128; i += 512) Ws[i] = __ldg(&w3[i]);
    __syncthreads();
    {
        // grp4 0..3 handle {7,7,6,6} channels starting at {3,10,17,23}
        const int obase = (grp4 < 2) ? (3 + grp4 * 7) : (17 + (grp4 - 2) * 6);
        const int cnt   = (grp4 < 2) ? 7 : 6;
        float dxv[7];
#pragma unroll
        for (int u = 0; u < 7; ++u) dxv[u] = 0.f;
#pragma unroll 2
        for (int k = 0; k < 128; ++k) {
            float h = H2s[k * 128 + pix];
#pragma unroll
            for (int u = 0; u < 7; ++u)
                dxv[u] = fmaf(Ws[(obase + u) * 128 + k], h, dxv[u]);
        }
        if (real) {
            int base = b * (kNCH * kPix) + px;
#pragma unroll
            for (int u = 0; u < 7; ++u) {
                if (u < cnt) {
                    int idx = base + (obase + u) * kPix;
                    dst[idx] = __ldg(&src[idx]) + dxv[u];
                }
            }
        }
    }
}

// ---------------------------------------------------------------------------
// reduce: mean over HW of channels 19..28, then softmax -> out (16, 10)
// ---------------------------------------------------------------------------
__global__ void __launch_bounds__(256) nca_reduce_kernel(float* __restrict__ out)
{
    int b = blockIdx.x;
    int tid = threadIdx.x;
    const float* st = g_state[0] + (b * kNCH + 19) * kPix;
    float acc[10];
#pragma unroll
    for (int c = 0; c < 10; ++c) acc[c] = 0.f;
    for (int i = tid; i < kPix; i += 256) {
#pragma unroll
        for (int c = 0; c < 10; ++c) acc[c] += st[c * kPix + i];
    }
#pragma unroll
    for (int c = 0; c < 10; ++c) {
#pragma unroll
        for (int off = 16; off > 0; off >>= 1)
            acc[c] += __shfl_xor_sync(0xffffffffu, acc[c], off);
    }
    __shared__ float sred[10][8];
    int wid = tid >> 5, lane = tid & 31;
    if (lane == 0) {
#pragma unroll
        for (int c = 0; c < 10; ++c) sred[c][wid] = acc[c];
    }
    __syncthreads();
    if (tid == 0) {
        float m[10];
        float mx = -1e30f;
#pragma unroll
        for (int c = 0; c < 10; ++c) {
            float s = 0.f;
#pragma unroll
            for (int w = 0; w < 8; ++w) s += sred[c][w];
            m[c] = s * (1.0f / 4096.0f);
            mx = fmaxf(mx, m[c]);
        }
        float den = 0.f;
        float e[10];
#pragma unroll
        for (int c = 0; c < 10; ++c) { e[c] = expf(m[c] - mx); den += e[c]; }
#pragma unroll
        for (int c = 0; c < 10; ++c) out[b * 10 + c] = e[c] / den;
    }
}

// ---------------------------------------------------------------------------
extern "C" void kernel_launch(void* const* d_in, const int* in_sizes, int n_in,
                              void* d_out, int out_size)
{
    (void)in_sizes; (void)n_in; (void)out_size;
    const float* x  = (const float*)d_in[0];
    const float* w1 = (const float*)d_in[1];
    const float* b1 = (const float*)d_in[2];
    const float* w2 = (const float*)d_in[3];
    const float* w3 = (const float*)d_in[4];
    float* out = (float*)d_out;

    cudaFuncSetAttribute(nca_step_kernel,
                         cudaFuncAttributeMaxDynamicSharedMemorySize, kSmemBytes);

    // hid-init key: fold_in(key(42), 10000)
    uint32_t hk0, hk1;
    threefry2x32(0u, 42u, 0u, 10000u, hk0, hk1);
    nca_init_kernel<<<(kStateElems + 255) / 256, 256>>>(x, hk0, hk1);

    for (int s = 0; s < kSteps; ++s) {
        uint32_t fk0, fk1;
        threefry2x32(0u, 42u, 0u, (uint32_t)s, fk0, fk1);
        nca_fire_kernel<<<64, 1024>>>(fk0, fk1, s, s & 1);
        nca_step_kernel<<<dim3(kTilesPerBatch, kBatch), 512, kSmemBytes>>>(
            w1, b1, w2, w3, (float)s / 100.0f, s, s & 1);
    }
    nca_reduce_kernel<<<16, 256>>>(out);
}

// round 15
// speedup vs baseline: 2.0943x; 1.0218x over previous
#include <cuda_runtime.h>
#include <cstdint>

// ---------------------------------------------------------------------------
// ClassificationNCA: 20-step NCA. Round 14:
//  - ALL fire/nonfire lists precomputed once (fire bits depend only on
//    (step, pixel)), globally compacted across batches (balanced tiles).
//  - per-step fire kernel deleted; non-firing copy-through fused into the
//    step kernel on surplus CTAs (run on idle wave-2 SMs).
//  - MLP body identical to round 13 (proven, fp32-pipe-bound).
// ---------------------------------------------------------------------------

#define kNCH 29
#define kBatch 16
#define kPix 4096
#define kTotalPix (kBatch * kPix)          /* 65536 */
#define kStateElems (kBatch * kNCH * kPix)
#define kSteps 20
#define kCap 36864                          /* 288 * 128 slot capacity */
#define kGridB 288

// smem layout (floats) — identical to round 4/13
#define kH1Off 16384              /* region A: P[88][128] / H2[128][128] */
#define kWsOff (kH1Off + 32768)   /* H1 = 256*128 */
#define kWsFloats 8192
#define kSmemFloats (kWsOff + kWsFloats)
#define kSmemBytes (kSmemFloats * 4) /* 229376 B -> 1 CTA/SM */

__device__ float g_state[2][kStateElems];
__device__ int g_fcnt[kSteps];
__device__ int g_nfcnt[kSteps];
__device__ uint32_t g_flist[kSteps][kCap];
__device__ uint32_t g_nflist[kSteps][kCap];

// ---------------------------------------------------------------------------
// packed f32x2 helpers
// ---------------------------------------------------------------------------
__device__ __forceinline__ unsigned long long pack2(float x, float y)
{
    unsigned long long r;
    asm("mov.b64 %0, {%1, %2};" : "=l"(r) : "f"(x), "f"(y));
    return r;
}
__device__ __forceinline__ unsigned long long ffma2(unsigned long long a,
                                                    unsigned long long b,
                                                    unsigned long long c)
{
    unsigned long long d;
    asm("fma.rn.f32x2 %0, %1, %2, %3;" : "=l"(d) : "l"(a), "l"(b), "l"(c));
    return d;
}
__device__ __forceinline__ float2 unpack2(unsigned long long v)
{
    float2 f;
    asm("mov.b64 {%0, %1}, %2;" : "=f"(f.x), "=f"(f.y) : "l"(v));
    return f;
}

// ---------------------------------------------------------------------------
// threefry2x32, JAX key schedule (20 rounds)
// ---------------------------------------------------------------------------
#define TF_ROUND(r) { x0 += x1; x1 = (x1 << (r)) | (x1 >> (32 - (r))); x1 ^= x0; }
__host__ __device__ inline void threefry2x32(uint32_t k0, uint32_t k1,
                                             uint32_t x0, uint32_t x1,
                                             uint32_t &o0, uint32_t &o1)
{
    uint32_t k2 = k0 ^ k1 ^ 0x1BD11BDAu;
    x0 += k0; x1 += k1;
    TF_ROUND(13) TF_ROUND(15) TF_ROUND(26) TF_ROUND(6)
    x0 += k1; x1 += k2 + 1u;
    TF_ROUND(17) TF_ROUND(29) TF_ROUND(16) TF_ROUND(24)
    x0 += k2; x1 += k0 + 2u;
    TF_ROUND(13) TF_ROUND(15) TF_ROUND(26) TF_ROUND(6)
    x0 += k0; x1 += k1 + 3u;
    TF_ROUND(17) TF_ROUND(29) TF_ROUND(16) TF_ROUND(24)
    x0 += k1; x1 += k2 + 4u;
    TF_ROUND(13) TF_ROUND(15) TF_ROUND(26) TF_ROUND(6)
    x0 += k2; x1 += k0 + 5u;
    o0 = x0; o1 = x1;
}

// XLA ErfInv (f32), Giles polynomial — matches jax.lax.erf_inv
__device__ inline float erfinv_f(float x)
{
    float w = -log1pf(-x * x);
    float p;
    if (w < 5.0f) {
        w -= 2.5f;
        p = 2.81022636e-08f;
        p = fmaf(p, w, 3.43273939e-07f);
        p = fmaf(p, w, -3.5233877e-06f);
        p = fmaf(p, w, -4.39150654e-06f);
        p = fmaf(p, w, 0.00021858087f);
        p = fmaf(p, w, -0.00125372503f);
        p = fmaf(p, w, -0.00417768164f);
        p = fmaf(p, w, 0.246640727f);
        p = fmaf(p, w, 1.50140941f);
    } else {
        w = sqrtf(w) - 3.0f;
        p = -0.000200214257f;
        p = fmaf(p, w, 0.000100950558f);
        p = fmaf(p, w, 0.00134934322f);
        p = fmaf(p, w, -0.00367342844f);
        p = fmaf(p, w, 0.00573950773f);
        p = fmaf(p, w, -0.0076224613f);
        p = fmaf(p, w, 0.00943887047f);
        p = fmaf(p, w, 1.00167406f);
        p = fmaf(p, w, 2.83297682f);
    }
    return p * x;
}

// ---------------------------------------------------------------------------
// init: channels 0-2 = image (both buffers), 3-18 = threefry normal, 19-28 = 0
// also zeroes the per-step list counters (per launch -> graph-replay safe).
// ---------------------------------------------------------------------------
__global__ void __launch_bounds__(256) nca_init_kernel(const float* __restrict__ x,
                                                       uint32_t hk0, uint32_t hk1)
{
    int e = blockIdx.x * 256 + threadIdx.x;
    if (e >= kStateElems) return;
    if (e < kSteps) { g_fcnt[e] = 0; g_nfcnt[e] = 0; }
    int b = e / (kNCH * kPix);
    int r = e - b * (kNCH * kPix);
    int c = r / kPix;
    int pix = r - c * kPix;

    if (c < 3) {
        float v = x[(b * 3 + c) * kPix + pix];
        g_state[0][e] = v;
        g_state[1][e] = v;
    } else if (c < 19) {
        const uint32_t HALF = 524288u;  // (16*16*4096)/2
        uint32_t i = (uint32_t)((b * 16 + (c - 3)) * kPix + pix);
        uint32_t lo = (i < HALF) ? i : (i - HALF);
        uint32_t o0, o1;
        threefry2x32(hk0, hk1, lo, lo + HALF, o0, o1);
        uint32_t bits = (i < HALF) ? o0 : o1;
        float f = __uint_as_float((bits >> 9) | 0x3f800000u) - 1.0f;
        const float LOV = -0.99999994f;               // nextafter(-1, 0)
        float u = fmaxf(LOV, f * 2.0f + LOV);         // (hi - lo) rounds to 2.0f
        float z = 1.41421356f * erfinv_f(u);
        g_state[0][e] = 0.5f + 0.225f * z;
    } else {
        g_state[0][e] = 0.0f;
    }
}

// ---------------------------------------------------------------------------
// list precompute: for every step, compact firing / non-firing pixel ids.
// grid (64, 20) x 1024. Fire bit depends only on (step, pixel).
// ---------------------------------------------------------------------------
__global__ void __launch_bounds__(1024) nca_lists_kernel()
{
    const int step = blockIdx.y;
    const int e = blockIdx.x * 1024 + threadIdx.x;   // 0..65535

    // fold_in(key(42), step)
    uint32_t fk0, fk1;
    threefry2x32(0u, 42u, 0u, (uint32_t)step, fk0, fk1);

    // fire: uniform < 0.5  <=>  top bit of bits == 0
    const uint32_t HALF = 32768u;
    uint32_t n = (uint32_t)e;
    uint32_t lo = (n < HALF) ? n : (n - HALF);
    uint32_t o0, o1;
    threefry2x32(fk0, fk1, lo, lo + HALF, o0, o1);
    uint32_t bits = (n < HALF) ? o0 : o1;
    bool fire = (bits & 0x80000000u) == 0u;

    unsigned m = __ballot_sync(0xffffffffu, fire);
    int lane = threadIdx.x & 31;
    int fb = 0, nb = 0;
    if (lane == 0) {
        fb = atomicAdd(&g_fcnt[step], __popc(m));
        nb = atomicAdd(&g_nfcnt[step], 32 - __popc(m));
    }
    fb = __shfl_sync(0xffffffffu, fb, 0);
    nb = __shfl_sync(0xffffffffu, nb, 0);

    if (fire)
        g_flist[step][fb + __popc(m & ((1u << lane) - 1u))] = (uint32_t)e;
    else
        g_nflist[step][nb + __popc(~m & ((1u << lane) - 1u))] = (uint32_t)e;
}

// ---------------------------------------------------------------------------
// fused step kernel: grid kGridB CTAs x 512 threads.
//   CTA < tiles        : MLP on 128 compacted firing slots (round-13 body)
//   CTA >= tiles       : copy-through worker for non-firing pixels
// ---------------------------------------------------------------------------
__global__ void __launch_bounds__(512, 1) nca_step_kernel(
    const float* __restrict__ w1, const float* __restrict__ b1,
    const float* __restrict__ w2, const float* __restrict__ w3,
    float tval, int step, int srcbuf)
{
    extern __shared__ float smem[];
    float* P   = smem;           // [88][128]
    float* H1s = smem + kH1Off;  // [256][128]
    float* H2s = smem;           // [128][128] (reuses P region)
    float* Ws  = smem + kWsOff;  // weight staging, 8192 floats

    const float* __restrict__ src = g_state[srcbuf];
    float* __restrict__ dst = g_state[srcbuf ^ 1];

    const int nf = g_fcnt[step];
    const int tiles = (nf + 127) >> 7;
    const int tid = threadIdx.x;

    if ((int)blockIdx.x >= tiles) {
        // ---- copy worker: non-firing pixels, channels 3..28 pass through ----
        const int W = kGridB - tiles;
        const int w = blockIdx.x - tiles;
        const int nn = g_nfcnt[step];
        for (int j = w * 512 + tid; j < nn; j += W * 512) {
            uint32_t e = g_nflist[step][j];
            int base = ((int)(e >> 12)) * (kNCH * kPix) + 3 * kPix + (int)(e & 4095u);
#pragma unroll
            for (int c = 0; c < 26; ++c)
                dst[base + c * kPix] = __ldg(&src[base + c * kPix]);
        }
        return;
    }

    const int pix  = tid & 127;          // slot-local index
    const int grp4 = tid >> 7;           // 0..3
    const int slot = blockIdx.x * 128 + pix;
    const bool real = slot < nf;
    const uint32_t e = g_flist[step][slot];   // stale-but-valid if !real
    const int b  = (int)(e >> 12);
    const int px = (int)(e & 4095u);
    const int gx = px & 63;
    const int gy = px >> 6;

    // ---- phase 1: perception (s, sobel_x, sobel_y, t) -> P ----
    {
        const float* sb = src + b * (kNCH * kPix);
        const int cbeg = grp4 * 8;
        const int cend = (cbeg + 8 < 29) ? cbeg + 8 : 29;
        const bool ym = gy > 0, yp = gy < 63, xm = gx > 0, xp = gx < 63;
        for (int c = cbeg; c < cend; ++c) {
            const float* sc = sb + c * kPix;
            float v11 = __ldg(&sc[gy * 64 + gx]);
            float v01 = ym ? __ldg(&sc[(gy - 1) * 64 + gx]) : 0.f;
            float v21 = yp ? __ldg(&sc[(gy + 1) * 64 + gx]) : 0.f;
            float v10 = xm ? __ldg(&sc[gy * 64 + gx - 1]) : 0.f;
            float v12 = xp ? __ldg(&sc[gy * 64 + gx + 1]) : 0.f;
            float v00 = (ym && xm) ? __ldg(&sc[(gy - 1) * 64 + gx - 1]) : 0.f;
            float v02 = (ym && xp) ? __ldg(&sc[(gy - 1) * 64 + gx + 1]) : 0.f;
            float v20 = (yp && xm) ? __ldg(&sc[(gy + 1) * 64 + gx - 1]) : 0.f;
            float v22 = (yp && xp) ? __ldg(&sc[(gy + 1) * 64 + gx + 1]) : 0.f;
            float sx = ((v02 - v00) + 2.0f * (v12 - v10) + (v22 - v20)) * 0.125f;
            float sy = ((v20 - v00) + 2.0f * (v21 - v01) + (v22 - v02)) * 0.125f;
            P[c * 128 + pix] = v11;
            P[(29 + c) * 128 + pix] = sx;
            P[(58 + c) * 128 + pix] = sy;
        }
        if (grp4 == 0) P[87 * 128 + pix] = tval;
    }

    const int og = tid >> 5;   // warp id 0..15 (uniform -> broadcast LDS)
    const int pb = (tid & 31) << 2;  // slot base, 4 slots / thread

    // ---- layer 1: h1 = leaky(W1 @ p + b1), 256 outs, k = 88 ----
    for (int chunk = 0; chunk < 2; ++chunk) {
        const int obase = og * 16 + chunk * 8;
        unsigned long long acc[4][4];
#pragma unroll
        for (int p = 0; p < 4; ++p) {
            unsigned long long bp = pack2(__ldg(&b1[obase + 2 * p]),
                                          __ldg(&b1[obase + 2 * p + 1]));
            acc[p][0] = bp; acc[p][1] = bp; acc[p][2] = bp; acc[p][3] = bp;
        }
        for (int ks = 0; ks < 88; ks += 44) {
            __syncthreads();
            // stage transposed: Ws[kk*128 + ol], ol -> weight row for this chunk
            for (int i = tid; i < 44 * 128; i += 512) {
                int kk = i >> 7;
                int ol = i & 127;
                int row = (ol >> 3) * 16 + chunk * 8 + (ol & 7);
                Ws[i] = __ldg(&w1[row * 88 + ks + kk]);
            }
            __syncthreads();
#pragma unroll 2
            for (int kk = 0; kk < 44; ++kk) {
                float4 pv = *reinterpret_cast<const float4*>(&P[(ks + kk) * 128 + pb]);
                const ulonglong2 wA = *reinterpret_cast<const ulonglong2*>(&Ws[kk * 128 + og * 8]);
                const ulonglong2 wB = *reinterpret_cast<const ulonglong2*>(&Ws[kk * 128 + og * 8 + 4]);
                unsigned long long px4[4];
                px4[0] = pack2(pv.x, pv.x); px4[1] = pack2(pv.y, pv.y);
                px4[2] = pack2(pv.z, pv.z); px4[3] = pack2(pv.w, pv.w);
#pragma unroll
                for (int j = 0; j < 4; ++j) {
                    acc[0][j] = ffma2(wA.x, px4[j], acc[0][j]);
                    acc[1][j] = ffma2(wA.y, px4[j], acc[1][j]);
                    acc[2][j] = ffma2(wB.x, px4[j], acc[2][j]);
                    acc[3][j] = ffma2(wB.y, px4[j], acc[3][j]);
                }
            }
        }
#pragma unroll
        for (int p = 0; p < 4; ++p) {
            float lo4[4], hi4[4];
#pragma unroll
            for (int j = 0; j < 4; ++j) {
                float2 f = unpack2(acc[p][j]);
                lo4[j] = f.x >= 0.f ? f.x : 0.01f * f.x;
                hi4[j] = f.y >= 0.f ? f.y : 0.01f * f.y;
            }
            *reinterpret_cast<float4*>(&H1s[(obase + 2 * p) * 128 + pb]) =
                make_float4(lo4[0], lo4[1], lo4[2], lo4[3]);
            *reinterpret_cast<float4*>(&H1s[(obase + 2 * p + 1) * 128 + pb]) =
                make_float4(hi4[0], hi4[1], hi4[2], hi4[3]);
        }
    }

    // ---- layer 2: h2 = leaky(W2 @ h1), 128 outs, k = 256 ----
    {
        const int obase = og * 8;
        unsigned long long acc[4][4];
#pragma unroll
        for (int p = 0; p < 4; ++p) {
            acc[p][0] = 0ull; acc[p][1] = 0ull; acc[p][2] = 0ull; acc[p][3] = 0ull;
        }
        for (int ks = 0; ks < 256; ks += 64) {
            __syncthreads();
            for (int i = tid; i < 64 * 128; i += 512) {
                int kk = i >> 7;
                int ol = i & 127;
                Ws[i] = __ldg(&w2[ol * 256 + ks + kk]);
            }
            __syncthreads();
#pragma unroll 2
            for (int kk = 0; kk < 64; ++kk) {
                float4 hv = *reinterpret_cast<const float4*>(&H1s[(ks + kk) * 128 + pb]);
                const ulonglong2 wA = *reinterpret_cast<const ulonglong2*>(&Ws[kk * 128 + og * 8]);
                const ulonglong2 wB = *reinterpret_cast<const ulonglong2*>(&Ws[kk * 128 + og * 8 + 4]);
                unsigned long long px4[4];
                px4[0] = pack2(hv.x, hv.x); px4[1] = pack2(hv.y, hv.y);
                px4[2] = pack2(hv.z, hv.z); px4[3] = pack2(hv.w, hv.w);
#pragma unroll
                for (int j = 0; j < 4; ++j) {
                    acc[0][j] = ffma2(wA.x, px4[j], acc[0][j]);
                    acc[1][j] = ffma2(wA.y, px4[j], acc[1][j]);
                    acc[2][j] = ffma2(wB.x, px4[j], acc[2][j]);
                    acc[3][j] = ffma2(wB.y, px4[j], acc[3][j]);
                }
            }
        }
#pragma unroll
        for (int p = 0; p < 4; ++p) {
            float lo4[4], hi4[4];
#pragma unroll
            for (int j = 0; j < 4; ++j) {
                float2 f = unpack2(acc[p][j]);
                lo4[j] = f.x >= 0.f ? f.x : 0.01f * f.x;
                hi4[j] = f.y >= 0.f ? f.y : 0.01f * f.y;
            }
            *reinterpret_cast<float4*>(&H2s[(obase + 2 * p) * 128 + pb]) =
                make_float4(lo4[0], lo4[1], lo4[2], lo4[3]);
            *reinterpret_cast<float4*>(&H2s[(obase + 2 * p + 1) * 128 + pb]) =
                make_float4(hi4[0], hi4[1], hi4[2], hi4[3]);
        }
    }

    // ---- layer 3 (channels 3..28) + unconditional update of firing px ----
    __syncthreads();
    for (int i = tid; i < 29 * 128; i += 512) Ws[i] = __ldg(&w3[i]);
    __syncthreads();
    {
        // grp4 0..3 handle {7,7,6,6} channels starting at {3,10,17,23}
        const int obase = (grp4 < 2) ? (3 + grp4 * 7) : (17 + (grp4 - 2) * 6);
        const int cnt   = (grp4 < 2) ? 7 : 6;
        float dxv[7];
#pragma unroll
        for (int u = 0; u < 7; ++u) dxv[u] = 0.f;
#pragma unroll 2
        for (int k = 0; k < 128; ++k) {
            float h = H2s[k * 128 + pix];
#pragma unroll
            for (int u = 0; u < 7; ++u)
                dxv[u] = fmaf(Ws[(obase + u) * 128 + k], h, dxv[u]);
        }
        if (real) {
            int base = b * (kNCH * kPix) + px;
#pragma unroll
            for (int u = 0; u < 7; ++u) {
                if (u < cnt) {
                    int idx = base + (obase + u) * kPix;
                    dst[idx] = __ldg(&src[idx]) + dxv[u];
                }
            }
        }
    }
}

// ---------------------------------------------------------------------------
// reduce: mean over HW of channels 19..28, then softmax -> out (16, 10)
// ---------------------------------------------------------------------------
__global__ void __launch_bounds__(256) nca_reduce_kernel(float* __restrict__ out)
{
    int b = blockIdx.x;
    int tid = threadIdx.x;
    const float* st = g_state[0] + (b * kNCH + 19) * kPix;
    float acc[10];
#pragma unroll
    for (int c = 0; c < 10; ++c) acc[c] = 0.f;
    for (int i = tid; i < kPix; i += 256) {
#pragma unroll
        for (int c = 0; c < 10; ++c) acc[c] += st[c * kPix + i];
    }
#pragma unroll
    for (int c = 0; c < 10; ++c) {
#pragma unroll
        for (int off = 16; off > 0; off >>= 1)
            acc[c] += __shfl_xor_sync(0xffffffffu, acc[c], off);
    }
    __shared__ float sred[10][8];
    int wid = tid >> 5, lane = tid & 31;
    if (lane == 0) {
#pragma unroll
        for (int c = 0; c < 10; ++c) sred[c][wid] = acc[c];
    }
    __syncthreads();
    if (tid == 0) {
        float m[10];
        float mx = -1e30f;
#pragma unroll
        for (int c = 0; c < 10; ++c) {
            float s = 0.f;
#pragma unroll
            for (int w = 0; w < 8; ++w) s += sred[c][w];
            m[c] = s * (1.0f / 4096.0f);
            mx = fmaxf(mx, m[c]);
        }
        float den = 0.f;
        float e[10];
#pragma unroll
        for (int c = 0; c < 10; ++c) { e[c] = expf(m[c] - mx); den += e[c]; }
#pragma unroll
        for (int c = 0; c < 10; ++c) out[b * 10 + c] = e[c] / den;
    }
}

// ---------------------------------------------------------------------------
extern "C" void kernel_launch(void* const* d_in, const int* in_sizes, int n_in,
                              void* d_out, int out_size)
{
    (void)in_sizes; (void)n_in; (void)out_size;
    const float* x  = (const float*)d_in[0];
    const float* w1 = (const float*)d_in[1];
    const float* b1 = (const float*)d_in[2];
    const float* w2 = (const float*)d_in[3];
    const float* w3 = (const float*)d_in[4];
    float* out = (float*)d_out;

    cudaFuncSetAttribute(nca_step_kernel,
                         cudaFuncAttributeMaxDynamicSharedMemorySize, kSmemBytes);

    // hid-init key: fold_in(key(42), 10000)
    uint32_t hk0, hk1;
    threefry2x32(0u, 42u, 0u, 10000u, hk0, hk1);
    nca_init_kernel<<<(kStateElems + 255) / 256, 256>>>(x, hk0, hk1);

    // precompute all 20 steps' fire/nonfire lists (state-independent)
    nca_lists_kernel<<<dim3(64, kSteps), 1024>>>();

    for (int s = 0; s < kSteps; ++s) {
        nca_step_kernel<<<kGridB, 512, kSmemBytes>>>(
            w1, b1, w2, w3, (float)s / 100.0f, s, s & 1);
    }
    nca_reduce_kernel<<<16, 256>>>(out);
}